// round 9
// baseline (speedup 1.0000x reference)
#include <cuda_runtime.h>
#include <cuda_fp16.h>
#include <math.h>

#define NN 50000
#define NE 800000
#define ET (NE + NN)
#define DI 128
#define DH 64
#define DOUT 40
#define SLOPE 0.2f
#define NBLOCK 296
#define NTHR 512
#define NWTOT (NBLOCK * (NTHR / 32))     // 4736 warps
#define CH 169                            // ceil(NN / NBLOCK)
#define GSTRIDE (NBLOCK * NTHR)

// ---------------- scratch ----------------
__device__ __half2 g_h16[NN * (DH / 2)];
__device__ float   g_as[NN];
__device__ float   g_ad[NN];
__device__ float   g_h1o[NN * DH];
__device__ int     g_deg[NN];            // zero-init; re-zeroed in P5 for next call
__device__ int     g_rowptr[NN + 1];
__device__ int     g_bsum[NBLOCK];
__device__ int     g_rank[ET];
__device__ int     g_esrc[ET];
__device__ unsigned g_barcnt;            // monotonic global-barrier counter

// ---------------- software global barrier (all 296 blocks resident) ----------
__device__ __forceinline__ void gsync() {
    __syncthreads();
    if (threadIdx.x == 0) {
        __threadfence();
        unsigned my = atomicAdd(&g_barcnt, 1u);
        unsigned need = (my / NBLOCK + 1u) * NBLOCK;
        while (*((volatile unsigned*)&g_barcnt) < need) __nanosleep(32);
        __threadfence();
    }
    __syncthreads();
}

// ---------------- phase: edge histogram (+rank) ----------------
__device__ void hist_phase(const int* __restrict__ ei) {
    int gt = blockIdx.x * NTHR + threadIdx.x;
    for (int t = gt; t < NE / 8 + NN; t += GSTRIDE) {
        if (t < NE / 8) {
            int4 a = *(const int4*)&ei[NE + t * 8];
            int4 b = *(const int4*)&ei[NE + t * 8 + 4];
            int r0 = atomicAdd(&g_deg[a.x], 1);
            int r1 = atomicAdd(&g_deg[a.y], 1);
            int r2 = atomicAdd(&g_deg[a.z], 1);
            int r3 = atomicAdd(&g_deg[a.w], 1);
            int r4 = atomicAdd(&g_deg[b.x], 1);
            int r5 = atomicAdd(&g_deg[b.y], 1);
            int r6 = atomicAdd(&g_deg[b.z], 1);
            int r7 = atomicAdd(&g_deg[b.w], 1);
            *(int4*)&g_rank[t * 8]     = make_int4(r0, r1, r2, r3);
            *(int4*)&g_rank[t * 8 + 4] = make_int4(r4, r5, r6, r7);
        } else {
            int n = t - NE / 8;
            g_rank[NE + n] = atomicAdd(&g_deg[n], 1);
        }
    }
}

// ---------------- phase: per-block chunk scan ----------------
__device__ void scan_local_phase(int* sh) {
    int t = threadIdx.x, lane = t & 31, wid = t >> 5;
    int base = blockIdx.x * CH;
    int i = base + t;
    int v = (t < CH && i < NN) ? g_deg[i] : 0;
    int sc = v;
#pragma unroll
    for (int off = 1; off < 32; off <<= 1) {
        int u = __shfl_up_sync(0xffffffffu, sc, off);
        if (lane >= off) sc += u;
    }
    if (lane == 31) sh[wid] = sc;
    __syncthreads();
    if (wid == 0) {
        int w0 = (lane < 16) ? sh[lane] : 0;
        int s = w0;
#pragma unroll
        for (int off = 1; off < 32; off <<= 1) {
            int u = __shfl_up_sync(0xffffffffu, s, off);
            if (lane >= off) s += u;
        }
        if (lane == 15) g_bsum[blockIdx.x] = s;   // block total
        if (lane < 16) sh[lane] = s - w0;          // exclusive warp offsets
    }
    __syncthreads();
    int ex = sc - v + sh[wid];
    if (t < CH && i < NN) g_rowptr[i] = ex;
}

// ---------------- phase: add block offsets ----------------
__device__ void add_off_phase(int* sh) {
    int t = threadIdx.x;
    if (t < 32) {
        int pre = 0;
        for (int i = t; i < NBLOCK; i += 32) {
            int sv = g_bsum[i];
            if (i < (int)blockIdx.x) pre += sv;
        }
#pragma unroll
        for (int off = 16; off; off >>= 1) pre += __shfl_xor_sync(0xffffffffu, pre, off);
        if (t == 0) sh[0] = pre;
    }
    __syncthreads();
    int pre = sh[0];
    int i = blockIdx.x * CH + t;
    if (t < CH && i < NN) g_rowptr[i] += pre;
    if (blockIdx.x == 0 && t == 0) g_rowptr[NN] = ET;
    __syncthreads();
}

// ---------------- phase: atomic-free scatter ----------------
__device__ void scatter_phase(const int* __restrict__ ei) {
    int gt = blockIdx.x * NTHR + threadIdx.x;
    for (int t = gt; t < NE / 8 + NN; t += GSTRIDE) {
        if (t < NE / 8) {
            int4 s0 = *(const int4*)&ei[t * 8];
            int4 s1 = *(const int4*)&ei[t * 8 + 4];
            int4 d0 = *(const int4*)&ei[NE + t * 8];
            int4 d1 = *(const int4*)&ei[NE + t * 8 + 4];
            int4 r0 = *(const int4*)&g_rank[t * 8];
            int4 r1 = *(const int4*)&g_rank[t * 8 + 4];
            g_esrc[g_rowptr[d0.x] + r0.x] = s0.x;
            g_esrc[g_rowptr[d0.y] + r0.y] = s0.y;
            g_esrc[g_rowptr[d0.z] + r0.z] = s0.z;
            g_esrc[g_rowptr[d0.w] + r0.w] = s0.w;
            g_esrc[g_rowptr[d1.x] + r1.x] = s1.x;
            g_esrc[g_rowptr[d1.y] + r1.y] = s1.y;
            g_esrc[g_rowptr[d1.z] + r1.z] = s1.z;
            g_esrc[g_rowptr[d1.w] + r1.w] = s1.w;
        } else {
            int n = t - NE / 8;
            g_esrc[g_rowptr[n] + g_rank[NE + n]] = n;
        }
    }
}

// ---------------- phase: GEMM + att dots + fp16 convert (64-node tiles) ------
template <int Din, int Dout, bool USE_X>
__device__ void gemm_att_phase(float* sx, const float* __restrict__ X,
                               const float* __restrict__ W,
                               const float* __restrict__ asrc,
                               const float* __restrict__ adst) {
    const float* src = USE_X ? X : g_h1o;
    int tid = threadIdx.x;
    const int NT = (NN + 63) / 64;
    for (int tile = blockIdx.x; tile < NT; tile += NBLOCK) {
        int base = tile * 64;
        for (int i = tid; i < 64 * (Din / 4); i += NTHR) {
            int node = base + i / (Din / 4);
            float4 v = (node < NN)
                ? ((const float4*)src)[(size_t)node * (Din / 4) + (i % (Din / 4))]
                : make_float4(0.f, 0.f, 0.f, 0.f);
            ((float4*)sx)[i] = v;
        }
        __syncthreads();

        int j = tid & 63;
        int n0 = tid >> 6;   // 0..7
        float acc[8];
#pragma unroll
        for (int i = 0; i < 8; i++) acc[i] = 0.f;
        if (j < Dout) {
            for (int k = 0; k < Din; k += 4) {
                float w0 = W[(k + 0) * Dout + j];
                float w1 = W[(k + 1) * Dout + j];
                float w2 = W[(k + 2) * Dout + j];
                float w3 = W[(k + 3) * Dout + j];
#pragma unroll
                for (int i = 0; i < 8; i++) {
                    int node = n0 + i * 8;
                    float4 xv = ((const float4*)sx)[node * (Din / 4) + (k >> 2)];
                    acc[i] += xv.x * w0 + xv.y * w1 + xv.z * w2 + xv.w * w3;
                }
            }
        }
        __syncthreads();           // done reading sx

        float* hacc = sx;          // reuse as h tile [64][Dout]
        if (j < Dout) {
#pragma unroll
            for (int i = 0; i < 8; i++) hacc[(n0 + i * 8) * Dout + j] = acc[i];
        }
        __syncthreads();

        // fp16 conversion
        for (int idx = tid; idx < 64 * (Dout / 2); idx += NTHR) {
            int node = idx / (Dout / 2), c = idx % (Dout / 2);
            if (base + node < NN) {
                float2 v = make_float2(hacc[node * Dout + 2 * c], hacc[node * Dout + 2 * c + 1]);
                g_h16[(size_t)(base + node) * (Dout / 2) + c] = __float22half2_rn(v);
            }
        }
        // att dots: warp per node
        int wid = tid >> 5, lane = tid & 31;
        for (int node = wid; node < 64; node += NTHR / 32) {
            float sa = 0.f, sd = 0.f;
            for (int c = lane; c < Dout; c += 32) {
                float h = hacc[node * Dout + c];
                sa += h * asrc[c];
                sd += h * adst[c];
            }
#pragma unroll
            for (int off = 16; off; off >>= 1) {
                sa += __shfl_down_sync(0xffffffffu, sa, off);
                sd += __shfl_down_sync(0xffffffffu, sd, off);
            }
            if (lane == 0 && base + node < NN) {
                g_as[base + node] = sa;
                g_ad[base + node] = sd;
            }
        }
        __syncthreads();
    }
}

// ---------------- phase: online-softmax aggregation (+epilogue) --------------
template <int D, bool FINAL>
__device__ void agg_phase(char* smemraw, const float* __restrict__ b,
                          float* __restrict__ out) {
    float (*sp_p)[32] = (float(*)[32])smemraw;
    int   (*sp_s)[32] = (int(*)[32])(smemraw + (NTHR / 32) * 32 * 4);
    int wl = threadIdx.x >> 5;
    int lane = threadIdx.x & 31;

    for (int w = blockIdx.x * (NTHR / 32) + wl; w < NN; w += NWTOT) {
        int beg = g_rowptr[w];
        int end = g_rowptr[w + 1];
        float ad_n = g_ad[w];

        float m = -INFINITY;
        float ssum = 0.f;
        float ax = 0.f, ay = 0.f;

        for (int j0 = beg; j0 < end; j0 += 32) {
            int j = j0 + lane;
            int s = 0;
            float e = -INFINITY;
            if (j < end) {
                s = g_esrc[j];
                e = g_as[s] + ad_n;
                e = e > 0.f ? e : SLOPE * e;
            }
            float tm = e;
#pragma unroll
            for (int off = 16; off; off >>= 1) tm = fmaxf(tm, __shfl_xor_sync(0xffffffffu, tm, off));
            float mnew = fmaxf(m, tm);
            float scale = __expf(m - mnew);
            ssum *= scale; ax *= scale; ay *= scale;
            m = mnew;

            float p = (j < end) ? __expf(e - m) : 0.f;
            ssum += p;
            sp_p[wl][lane] = p;
            sp_s[wl][lane] = s;
            __syncwarp();
            int cnt = min(32, end - j0);
            if (lane < D / 2) {
#pragma unroll 8
                for (int k = 0; k < cnt; k++) {
                    float pk = sp_p[wl][k];
                    int   sk = sp_s[wl][k];
                    float2 hv = __half22float2(g_h16[(size_t)sk * (D / 2) + lane]);
                    ax += pk * hv.x;
                    ay += pk * hv.y;
                }
            }
            __syncwarp();
        }
#pragma unroll
        for (int off = 16; off; off >>= 1) ssum += __shfl_xor_sync(0xffffffffu, ssum, off);
        float inv = 1.f / (ssum + 1e-16f);

        if (!FINAL) {
            float v0 = ax * inv + b[2 * lane];
            float v1 = ay * inv + b[2 * lane + 1];
            float2 o;
            o.x = v0 > 0.f ? v0 : 0.f;
            o.y = v1 > 0.f ? v1 : 0.f;
            ((float2*)g_h1o)[(size_t)w * (D / 2) + lane] = o;
        } else {
            float va = -INFINITY, vb = -INFINITY;
            if (lane < D / 2) {
                va = ax * inv + b[2 * lane];
                vb = ay * inv + b[2 * lane + 1];
            }
            float mx = fmaxf(va, vb);
#pragma unroll
            for (int off = 16; off; off >>= 1) mx = fmaxf(mx, __shfl_xor_sync(0xffffffffu, mx, off));
            float se = (lane < D / 2) ? (__expf(va - mx) + __expf(vb - mx)) : 0.f;
#pragma unroll
            for (int off = 16; off; off >>= 1) se += __shfl_xor_sync(0xffffffffu, se, off);
            float lse = mx + logf(se);
            if (lane < D / 2) {
                float2 o;
                o.x = va - lse;
                o.y = vb - lse;
                ((float2*)out)[(size_t)w * (D / 2) + lane] = o;
            }
        }
    }
}

// ---------------- the single persistent kernel ----------------
__global__ __launch_bounds__(NTHR, 2)
void fused_gat_kernel(const float* __restrict__ x, const int* __restrict__ ei,
                      const float* __restrict__ W1, const float* __restrict__ as1,
                      const float* __restrict__ ad1, const float* __restrict__ b1,
                      const float* __restrict__ W2, const float* __restrict__ as2,
                      const float* __restrict__ ad2, const float* __restrict__ b2,
                      float* __restrict__ out) {
    extern __shared__ char smem[];

    // P1: layer-1 GEMM(+att,+fp16) and edge histogram (independent; packed)
    gemm_att_phase<DI, DH, true>((float*)smem, x, W1, as1, ad1);
    hist_phase(ei);
    gsync();

    // P2: per-block chunk scan
    scan_local_phase((int*)smem);
    gsync();

    // P3: add block offsets
    add_off_phase((int*)smem);
    gsync();

    // P4: scatter edges into CSR
    scatter_phase(ei);
    gsync();

    // P5: layer-1 aggregation (+relu epilogue) ; re-zero deg for next call
    agg_phase<DH, false>(smem, b1, nullptr);
    {
        int gt = blockIdx.x * NTHR + threadIdx.x;
        for (int i = gt; i < NN; i += GSTRIDE) g_deg[i] = 0;
    }
    gsync();

    // P6: layer-2 GEMM(+att,+fp16)
    gemm_att_phase<DH, DOUT, false>((float*)smem, nullptr, W2, as2, ad2);
    gsync();

    // P7: layer-2 aggregation + log_softmax
    agg_phase<DOUT, true>(smem, b2, out);
}

extern "C" void kernel_launch(void* const* d_in, const int* in_sizes, int n_in,
                              void* d_out, int out_size) {
    const float* x   = (const float*)d_in[0];
    const int*   ei  = (const int*)d_in[1];
    const float* W1  = (const float*)d_in[2];
    const float* as1 = (const float*)d_in[3];
    const float* ad1 = (const float*)d_in[4];
    const float* b1  = (const float*)d_in[5];
    const float* W2  = (const float*)d_in[6];
    const float* as2 = (const float*)d_in[7];
    const float* ad2 = (const float*)d_in[8];
    const float* b2  = (const float*)d_in[9];
    float* out = (float*)d_out;

    const int SMEM = 64 * DI * 4;   // 32KB: gemm1 tile; superset of all phase needs
    fused_gat_kernel<<<NBLOCK, NTHR, SMEM>>>(x, ei, W1, as1, ad1, b1,
                                             W2, as2, ad2, b2, out);
}

// round 10
// speedup vs baseline: 1.4037x; 1.4037x over previous
#include <cuda_runtime.h>
#include <cuda_fp16.h>
#include <math.h>

#define NN 50000
#define NE 800000
#define ET (NE + NN)
#define DI 128
#define DH 64
#define DOUT 40
#define SLOPE 0.2f
#define SCB 1024
#define NBLK 49            // ceil(50000/1024)

typedef unsigned long long u64;

__device__ __forceinline__ u64 pack2(float lo, float hi) {
    u64 r; asm("mov.b64 %0,{%1,%2};" : "=l"(r) : "f"(lo), "f"(hi)); return r;
}
__device__ __forceinline__ float2 unpack2(u64 a) {
    float2 f; asm("mov.b64 {%0,%1}, %2;" : "=f"(f.x), "=f"(f.y) : "l"(a)); return f;
}
__device__ __forceinline__ void fma2(u64& a, u64 x, u64 w) {
    asm("fma.rn.f32x2 %0, %1, %2, %0;" : "+l"(a) : "l"(x), "l"(w));
}

// ---------------- scratch ----------------
__device__ __half2 g_h16[NN * (DH / 2)];
__device__ float   g_as[NN];
__device__ float   g_ad[NN];
__device__ float   g_h1o[NN * DH];
__device__ int     g_deg[NN];        // starts zero; re-zeroed by scatter each call
__device__ int     g_rowptr[NN + 1];
__device__ int     g_bsum[NBLK];
__device__ int     g_rank[ET];
__device__ int     g_esrc[ET];

// ---------------- CSR build ----------------
__global__ void hist_kernel(const int* __restrict__ ei) {
    int t = blockIdx.x * blockDim.x + threadIdx.x;
    if (t < NE / 8) {
        int4 a = *(const int4*)&ei[NE + t * 8];
        int4 b = *(const int4*)&ei[NE + t * 8 + 4];
        int r0 = atomicAdd(&g_deg[a.x], 1);
        int r1 = atomicAdd(&g_deg[a.y], 1);
        int r2 = atomicAdd(&g_deg[a.z], 1);
        int r3 = atomicAdd(&g_deg[a.w], 1);
        int r4 = atomicAdd(&g_deg[b.x], 1);
        int r5 = atomicAdd(&g_deg[b.y], 1);
        int r6 = atomicAdd(&g_deg[b.z], 1);
        int r7 = atomicAdd(&g_deg[b.w], 1);
        *(int4*)&g_rank[t * 8]     = make_int4(r0, r1, r2, r3);
        *(int4*)&g_rank[t * 8 + 4] = make_int4(r4, r5, r6, r7);
    } else {
        int n = t - NE / 8;
        if (n < NN) g_rank[NE + n] = atomicAdd(&g_deg[n], 1);
    }
}

__global__ void scan_local_kernel() {
    __shared__ int wsum[32];
    int t = threadIdx.x, lane = t & 31, wid = t >> 5;
    int i = blockIdx.x * SCB + t;
    int v = (i < NN) ? g_deg[i] : 0;
    int sc = v;
#pragma unroll
    for (int off = 1; off < 32; off <<= 1) {
        int u = __shfl_up_sync(0xffffffffu, sc, off);
        if (lane >= off) sc += u;
    }
    if (lane == 31) wsum[wid] = sc;
    __syncthreads();
    if (wid == 0) {
        int w0 = wsum[lane];
        int s = w0;
#pragma unroll
        for (int off = 1; off < 32; off <<= 1) {
            int u = __shfl_up_sync(0xffffffffu, s, off);
            if (lane >= off) s += u;
        }
        wsum[lane] = s - w0;
    }
    __syncthreads();
    int ex = sc - v + wsum[wid];
    if (i < NN) g_rowptr[i] = ex;
    if (t == SCB - 1) g_bsum[blockIdx.x] = ex + v;
}

__global__ void add_off_kernel() {
    __shared__ int sh[2];
    int t = threadIdx.x, bid = blockIdx.x;
    if (t < 32) {
        int a = (t < NBLK) ? g_bsum[t] : 0;
        int b = (t + 32 < NBLK) ? g_bsum[t + 32] : 0;
        int pa = ((t < bid) ? a : 0) + ((t + 32 < bid) ? b : 0);
        int ta = a + b;
#pragma unroll
        for (int off = 16; off; off >>= 1) {
            pa += __shfl_xor_sync(0xffffffffu, pa, off);
            ta += __shfl_xor_sync(0xffffffffu, ta, off);
        }
        if (t == 0) { sh[0] = pa; sh[1] = ta; }
    }
    __syncthreads();
    int pre = sh[0];
    int i = bid * SCB + t;
    if (i < NN) g_rowptr[i] += pre;
    if (bid == NBLK - 1 && t == 0) g_rowptr[NN] = sh[1];
}

// atomic-free scatter; also re-zeroes g_deg for the next call (deg is dead here)
__global__ void scatter_kernel(const int* __restrict__ ei) {
    int t = blockIdx.x * blockDim.x + threadIdx.x;
    if (t < NE / 8) {
        int4 s0 = *(const int4*)&ei[t * 8];
        int4 s1 = *(const int4*)&ei[t * 8 + 4];
        int4 d0 = *(const int4*)&ei[NE + t * 8];
        int4 d1 = *(const int4*)&ei[NE + t * 8 + 4];
        int4 r0 = *(const int4*)&g_rank[t * 8];
        int4 r1 = *(const int4*)&g_rank[t * 8 + 4];
        g_esrc[g_rowptr[d0.x] + r0.x] = s0.x;
        g_esrc[g_rowptr[d0.y] + r0.y] = s0.y;
        g_esrc[g_rowptr[d0.z] + r0.z] = s0.z;
        g_esrc[g_rowptr[d0.w] + r0.w] = s0.w;
        g_esrc[g_rowptr[d1.x] + r1.x] = s1.x;
        g_esrc[g_rowptr[d1.y] + r1.y] = s1.y;
        g_esrc[g_rowptr[d1.z] + r1.z] = s1.z;
        g_esrc[g_rowptr[d1.w] + r1.w] = s1.w;
    } else {
        int n = t - NE / 8;
        if (n < NN) g_esrc[g_rowptr[n] + g_rank[NE + n]] = n;
    }
    int stride = gridDim.x * blockDim.x;
    for (int i = t; i < NN; i += stride) g_deg[i] = 0;
}

// ---------------- f32x2 GEMM + att dots + fp16 convert ----------------
// 64-node tile, 256 threads. smem: sxd[Din][64] duplicated-{x,x} u64; swp[Din][Dout/2] u64.
// Thread: warp w owns nodes w*8..w*8+7 (broadcast x), lane = colpair (conflict-free w).
template <int Din, int Dout, bool USE_X>
__global__ __launch_bounds__(256)
void gemm_att_kernel(const float* __restrict__ X, const float* __restrict__ W,
                     const float* __restrict__ asrc, const float* __restrict__ adst) {
    extern __shared__ u64 smem_u64[];
    u64* sxd = smem_u64;                      // Din*64
    u64* swp = smem_u64 + Din * 64;           // Din*(Dout/2)
    const float* src = USE_X ? X : g_h1o;
    int tid = threadIdx.x;
    int base = blockIdx.x * 64;

    for (int i = tid; i < 64 * (Din / 4); i += 256) {
        int node = i / (Din / 4);
        int k4 = (i % (Din / 4)) * 4;
        int gn = base + node;
        float4 v = (gn < NN) ? ((const float4*)src)[(size_t)gn * (Din / 4) + (k4 >> 2)]
                             : make_float4(0.f, 0.f, 0.f, 0.f);
        sxd[(k4 + 0) * 64 + node] = pack2(v.x, v.x);
        sxd[(k4 + 1) * 64 + node] = pack2(v.y, v.y);
        sxd[(k4 + 2) * 64 + node] = pack2(v.z, v.z);
        sxd[(k4 + 3) * 64 + node] = pack2(v.w, v.w);
    }
    for (int i = tid; i < Din * (Dout / 2); i += 256)
        swp[i] = ((const u64*)W)[i];          // natural col-pairs, rows 8B-aligned
    __syncthreads();

    int c2 = tid & 31;          // colpair (Dout=64: all 32; Dout=40: c2<20 active)
    int g = tid >> 5;           // warp id = node group
    bool active = c2 < Dout / 2;
    u64 acc[8];
#pragma unroll
    for (int n = 0; n < 8; n++) acc[n] = 0ull;

#pragma unroll 4
    for (int k = 0; k < Din; k++) {
        u64 w2 = active ? swp[k * (Dout / 2) + c2] : 0ull;
        const u64* xr = &sxd[k * 64 + g * 8];
        fma2(acc[0], xr[0], w2);
        fma2(acc[1], xr[1], w2);
        fma2(acc[2], xr[2], w2);
        fma2(acc[3], xr[3], w2);
        fma2(acc[4], xr[4], w2);
        fma2(acc[5], xr[5], w2);
        fma2(acc[6], xr[6], w2);
        fma2(acc[7], xr[7], w2);
    }
    __syncthreads();            // done with sxd/swp

    float* hs = (float*)smem_u64;   // h tile [64][Dout]
    if (active) {
#pragma unroll
        for (int n = 0; n < 8; n++) {
            float2 v = unpack2(acc[n]);
            hs[(g * 8 + n) * Dout + 2 * c2]     = v.x;
            hs[(g * 8 + n) * Dout + 2 * c2 + 1] = v.y;
        }
    }
    __syncthreads();

    // fp16 conversion (coalesced half2 stores)
    for (int idx = tid; idx < 64 * (Dout / 2); idx += 256) {
        int node = idx / (Dout / 2), c = idx % (Dout / 2);
        if (base + node < NN) {
            float2 v = make_float2(hs[node * Dout + 2 * c], hs[node * Dout + 2 * c + 1]);
            g_h16[(size_t)(base + node) * (Dout / 2) + c] = __float22half2_rn(v);
        }
    }
    // att dots: warp per node
    int lane = tid & 31;
    for (int node = g; node < 64; node += 8) {
        float sa = 0.f, sd = 0.f;
        for (int c = lane; c < Dout; c += 32) {
            float h = hs[node * Dout + c];
            sa += h * asrc[c];
            sd += h * adst[c];
        }
#pragma unroll
        for (int off = 16; off; off >>= 1) {
            sa += __shfl_down_sync(0xffffffffu, sa, off);
            sd += __shfl_down_sync(0xffffffffu, sd, off);
        }
        if (lane == 0 && base + node < NN) {
            g_as[base + node] = sa;
            g_ad[base + node] = sd;
        }
    }
}

// ---------------- fused online-softmax aggregation (+epilogue) ----------------
template <int D, bool FINAL>
__global__ void agg_kernel(const float* __restrict__ b, float* __restrict__ out) {
    __shared__ float sp_p[8][32];
    __shared__ int   sp_s[8][32];
    int wl = threadIdx.x >> 5;
    int w = (blockIdx.x * blockDim.x + threadIdx.x) >> 5;
    int lane = threadIdx.x & 31;
    if (w >= NN) return;
    int beg = g_rowptr[w];
    int end = g_rowptr[w + 1];
    float ad_n = g_ad[w];

    float m = -INFINITY;
    float ssum = 0.f;
    float ax = 0.f, ay = 0.f;

    for (int j0 = beg; j0 < end; j0 += 32) {
        int j = j0 + lane;
        int s = 0;
        float e = -INFINITY;
        if (j < end) {
            s = g_esrc[j];
            e = g_as[s] + ad_n;
            e = e > 0.f ? e : SLOPE * e;
        }
        float tm = e;
#pragma unroll
        for (int off = 16; off; off >>= 1) tm = fmaxf(tm, __shfl_xor_sync(0xffffffffu, tm, off));
        float mnew = fmaxf(m, tm);
        float scale = __expf(m - mnew);
        ssum *= scale; ax *= scale; ay *= scale;
        m = mnew;

        float p = (j < end) ? __expf(e - m) : 0.f;
        ssum += p;
        sp_p[wl][lane] = p;
        sp_s[wl][lane] = s;
        __syncwarp();
        int cnt = min(32, end - j0);
        if (lane < D / 2) {
#pragma unroll 8
            for (int k = 0; k < cnt; k++) {
                float pk = sp_p[wl][k];
                int   sk = sp_s[wl][k];
                float2 hv = __half22float2(g_h16[(size_t)sk * (D / 2) + lane]);
                ax += pk * hv.x;
                ay += pk * hv.y;
            }
        }
        __syncwarp();
    }
#pragma unroll
    for (int off = 16; off; off >>= 1) ssum += __shfl_xor_sync(0xffffffffu, ssum, off);
    float inv = 1.f / (ssum + 1e-16f);

    if (!FINAL) {
        float v0 = ax * inv + b[2 * lane];
        float v1 = ay * inv + b[2 * lane + 1];
        float2 o;
        o.x = v0 > 0.f ? v0 : 0.f;
        o.y = v1 > 0.f ? v1 : 0.f;
        ((float2*)g_h1o)[(size_t)w * (D / 2) + lane] = o;
    } else {
        float va = -INFINITY, vb = -INFINITY;
        if (lane < D / 2) {
            va = ax * inv + b[2 * lane];
            vb = ay * inv + b[2 * lane + 1];
        }
        float mx = fmaxf(va, vb);
#pragma unroll
        for (int off = 16; off; off >>= 1) mx = fmaxf(mx, __shfl_xor_sync(0xffffffffu, mx, off));
        float se = (lane < D / 2) ? (__expf(va - mx) + __expf(vb - mx)) : 0.f;
#pragma unroll
        for (int off = 16; off; off >>= 1) se += __shfl_xor_sync(0xffffffffu, se, off);
        float lse = mx + logf(se);
        if (lane < D / 2) {
            float2 o;
            o.x = va - lse;
            o.y = vb - lse;
            ((float2*)out)[(size_t)w * (D / 2) + lane] = o;
        }
    }
}

extern "C" void kernel_launch(void* const* d_in, const int* in_sizes, int n_in,
                              void* d_out, int out_size) {
    const float* x   = (const float*)d_in[0];
    const int*   ei  = (const int*)d_in[1];
    const float* W1  = (const float*)d_in[2];
    const float* as1 = (const float*)d_in[3];
    const float* ad1 = (const float*)d_in[4];
    const float* b1  = (const float*)d_in[5];
    const float* W2  = (const float*)d_in[6];
    const float* as2 = (const float*)d_in[7];
    const float* ad2 = (const float*)d_in[8];
    const float* b2  = (const float*)d_in[9];
    float* out = (float*)d_out;

    static cudaStream_t s2 = nullptr;
    static cudaEvent_t evFork = nullptr, evCSR = nullptr;
    static bool inited = false;
    if (!inited) {
        cudaStreamCreateWithFlags(&s2, cudaStreamNonBlocking);
        cudaEventCreateWithFlags(&evFork, cudaEventDisableTiming);
        cudaEventCreateWithFlags(&evCSR, cudaEventDisableTiming);
        const int SM1 = DI * 64 * 8 + DI * (DH / 2) * 8;      // 98304
        cudaFuncSetAttribute(gemm_att_kernel<DI, DH, true>,
                             cudaFuncAttributeMaxDynamicSharedMemorySize, SM1);
        inited = true;
    }

    const int TB = 256;
    int grid_edges = (NE / 8 + NN + TB - 1) / TB;
    int grid_warp_nodes = (NN * 32 + TB - 1) / TB;
    int grid_nodes64 = (NN + 63) / 64;
    const int SM1 = DI * 64 * 8 + DI * (DH / 2) * 8;          // 98304
    const int SM2 = DH * 64 * 8 + DH * (DOUT / 2) * 8;        // 43008

    // fork: CSR build on s2, concurrent with layer-1 GEMM on main
    cudaEventRecord(evFork, 0);
    cudaStreamWaitEvent(s2, evFork, 0);

    hist_kernel<<<grid_edges, TB, 0, s2>>>(ei);
    scan_local_kernel<<<NBLK, SCB, 0, s2>>>();
    add_off_kernel<<<NBLK, SCB, 0, s2>>>();
    scatter_kernel<<<grid_edges, TB, 0, s2>>>(ei);
    cudaEventRecord(evCSR, s2);

    // layer 1 GEMM (+att, fp16) on main
    gemm_att_kernel<DI, DH, true><<<grid_nodes64, 256, SM1>>>(x, W1, as1, ad1);

    cudaStreamWaitEvent(0, evCSR, 0);
    agg_kernel<DH, false><<<grid_warp_nodes, TB>>>(b1, nullptr);

    // layer 2
    gemm_att_kernel<DH, DOUT, false><<<grid_nodes64, 256, SM2>>>(nullptr, W2, as2, ad2);
    agg_kernel<DOUT, true><<<grid_warp_nodes, TB>>>(b2, out);
}

// round 12
// speedup vs baseline: 1.8684x; 1.3310x over previous
#include <cuda_runtime.h>
#include <cuda_fp16.h>
#include <math.h>

#define NN 50000
#define NE 800000
#define DI 128
#define DH 64
#define DOUT 40
#define SLOPE 0.2f
#define SCB 1024
#define NBLK 49            // ceil(50000/1024)

// ---------------- scratch ----------------
__device__ __half2 g_h16[NN * (DH / 2)];
__device__ float   g_as[NN];
__device__ float   g_ad[NN];
__device__ float   g_h1o[NN * DH];
__device__ int     g_deg[NN];        // starts zero; re-zeroed by scatter each call
__device__ int     g_rowptr[NN + 1];
__device__ int     g_bsum[NBLK];
__device__ int     g_rank[NE];
__device__ int     g_esrc[NE];

// ---------------- CSR build (real edges only; self loops handled in agg) -----
__global__ void hist_kernel(const int* __restrict__ ei) {
    int t = blockIdx.x * blockDim.x + threadIdx.x;
    if (t >= NE / 8) return;
    int4 a = *(const int4*)&ei[NE + t * 8];
    int4 b = *(const int4*)&ei[NE + t * 8 + 4];
    int r0 = atomicAdd(&g_deg[a.x], 1);
    int r1 = atomicAdd(&g_deg[a.y], 1);
    int r2 = atomicAdd(&g_deg[a.z], 1);
    int r3 = atomicAdd(&g_deg[a.w], 1);
    int r4 = atomicAdd(&g_deg[b.x], 1);
    int r5 = atomicAdd(&g_deg[b.y], 1);
    int r6 = atomicAdd(&g_deg[b.z], 1);
    int r7 = atomicAdd(&g_deg[b.w], 1);
    *(int4*)&g_rank[t * 8]     = make_int4(r0, r1, r2, r3);
    *(int4*)&g_rank[t * 8 + 4] = make_int4(r4, r5, r6, r7);
}

__global__ void scan_local_kernel() {
    __shared__ int wsum[32];
    int t = threadIdx.x, lane = t & 31, wid = t >> 5;
    int i = blockIdx.x * SCB + t;
    int v = (i < NN) ? g_deg[i] : 0;
    int sc = v;
#pragma unroll
    for (int off = 1; off < 32; off <<= 1) {
        int u = __shfl_up_sync(0xffffffffu, sc, off);
        if (lane >= off) sc += u;
    }
    if (lane == 31) wsum[wid] = sc;
    __syncthreads();
    if (wid == 0) {
        int w0 = wsum[lane];
        int s = w0;
#pragma unroll
        for (int off = 1; off < 32; off <<= 1) {
            int u = __shfl_up_sync(0xffffffffu, s, off);
            if (lane >= off) s += u;
        }
        wsum[lane] = s - w0;
    }
    __syncthreads();
    int ex = sc - v + wsum[wid];
    if (i < NN) g_rowptr[i] = ex;
    if (t == SCB - 1) g_bsum[blockIdx.x] = ex + v;
}

__global__ void add_off_kernel() {
    __shared__ int sh[2];
    int t = threadIdx.x, bid = blockIdx.x;
    if (t < 32) {
        int a = (t < NBLK) ? g_bsum[t] : 0;
        int b = (t + 32 < NBLK) ? g_bsum[t + 32] : 0;
        int pa = ((t < bid) ? a : 0) + ((t + 32 < bid) ? b : 0);
        int ta = a + b;
#pragma unroll
        for (int off = 16; off; off >>= 1) {
            pa += __shfl_xor_sync(0xffffffffu, pa, off);
            ta += __shfl_xor_sync(0xffffffffu, ta, off);
        }
        if (t == 0) { sh[0] = pa; sh[1] = ta; }
    }
    __syncthreads();
    int pre = sh[0];
    int i = bid * SCB + t;
    if (i < NN) g_rowptr[i] += pre;
    if (bid == NBLK - 1 && t == 0) g_rowptr[NN] = sh[1];
}

// atomic-free scatter; also re-zeroes g_deg for the next call
__global__ void scatter_kernel(const int* __restrict__ ei) {
    int t = blockIdx.x * blockDim.x + threadIdx.x;
    if (t < NE / 8) {
        int4 s0 = *(const int4*)&ei[t * 8];
        int4 s1 = *(const int4*)&ei[t * 8 + 4];
        int4 d0 = *(const int4*)&ei[NE + t * 8];
        int4 d1 = *(const int4*)&ei[NE + t * 8 + 4];
        int4 r0 = *(const int4*)&g_rank[t * 8];
        int4 r1 = *(const int4*)&g_rank[t * 8 + 4];
        g_esrc[g_rowptr[d0.x] + r0.x] = s0.x;
        g_esrc[g_rowptr[d0.y] + r0.y] = s0.y;
        g_esrc[g_rowptr[d0.z] + r0.z] = s0.z;
        g_esrc[g_rowptr[d0.w] + r0.w] = s0.w;
        g_esrc[g_rowptr[d1.x] + r1.x] = s1.x;
        g_esrc[g_rowptr[d1.y] + r1.y] = s1.y;
        g_esrc[g_rowptr[d1.z] + r1.z] = s1.z;
        g_esrc[g_rowptr[d1.w] + r1.w] = s1.w;
    }
    int stride = gridDim.x * blockDim.x;
    for (int i = t; i < NN; i += stride) g_deg[i] = 0;
}

// ---------------- fused GEMM + att dots + fp16 convert ----------------
template <int Din, int Dout, bool USE_X>
__global__ void gemm_att_kernel(const float* __restrict__ X, const float* __restrict__ W,
                                const float* __restrict__ asrc, const float* __restrict__ adst) {
    __shared__ float sx[32 * Din];   // x tile, later reused as h tile
    const float* src = USE_X ? X : g_h1o;
    int base = blockIdx.x * 32;
    int tid = threadIdx.x;
    const int nthr = Dout * 4;

    for (int i = tid; i < 32 * (Din / 4); i += nthr) {
        int node = base + i / (Din / 4);
        float4 v = (node < NN) ? ((const float4*)src)[(size_t)node * (Din / 4) + (i % (Din / 4))]
                               : make_float4(0.f, 0.f, 0.f, 0.f);
        ((float4*)sx)[i] = v;
    }
    __syncthreads();

    int j = tid % Dout;
    int n0 = tid / Dout;
    float acc[8];
#pragma unroll
    for (int i = 0; i < 8; i++) acc[i] = 0.f;

    for (int k = 0; k < Din; k += 4) {
        float w0 = W[(k + 0) * Dout + j];
        float w1 = W[(k + 1) * Dout + j];
        float w2 = W[(k + 2) * Dout + j];
        float w3 = W[(k + 3) * Dout + j];
#pragma unroll
        for (int i = 0; i < 8; i++) {
            int node = n0 + i * 4;
            float4 xv = ((const float4*)sx)[node * (Din / 4) + (k >> 2)];
            acc[i] += xv.x * w0 + xv.y * w1 + xv.z * w2 + xv.w * w3;
        }
    }
    __syncthreads();

    float* hacc = sx;               // reuse as h tile [32][Dout]
#pragma unroll
    for (int i = 0; i < 8; i++) hacc[(n0 + i * 4) * Dout + j] = acc[i];
    __syncthreads();

    for (int idx = tid; idx < 32 * (Dout / 2); idx += nthr) {
        int node = idx / (Dout / 2), c = idx % (Dout / 2);
        if (base + node < NN) {
            float2 v = make_float2(hacc[node * Dout + 2 * c], hacc[node * Dout + 2 * c + 1]);
            g_h16[(size_t)(base + node) * (Dout / 2) + c] = __float22half2_rn(v);
        }
    }

    int wid = tid >> 5, lane = tid & 31, nw = nthr / 32;
    for (int node = wid; node < 32; node += nw) {
        float sa = 0.f, sd = 0.f;
        for (int c = lane; c < Dout; c += 32) {
            float h = hacc[node * Dout + c];
            sa += h * asrc[c];
            sd += h * adst[c];
        }
#pragma unroll
        for (int off = 16; off; off >>= 1) {
            sa += __shfl_down_sync(0xffffffffu, sa, off);
            sd += __shfl_down_sync(0xffffffffu, sd, off);
        }
        if (lane == 0 && base + node < NN) {
            g_as[base + node] = sa;
            g_ad[base + node] = sd;
        }
    }
}

// ---------------- fused online-softmax aggregation (+epilogue) ----------------
// self loop folded into init: m=e_self; ssum=1 contributed by lane 0 ONLY
// (ssum is warp-reduced at the end); features per-lane from h16[w].
template <int D, bool FINAL>
__global__ void agg_kernel(const float* __restrict__ b, float* __restrict__ out) {
    __shared__ float sp_p[8][32];
    __shared__ int   sp_s[8][32];
    int wl = threadIdx.x >> 5;
    int w = (blockIdx.x * blockDim.x + threadIdx.x) >> 5;
    int lane = threadIdx.x & 31;
    if (w >= NN) return;
    int beg = g_rowptr[w];
    int end = g_rowptr[w + 1];
    float ad_n = g_ad[w];

    float es = g_as[w] + ad_n;
    es = es > 0.f ? es : SLOPE * es;
    float m = es;
    float ssum = (lane == 0) ? 1.f : 0.f;      // self edge p=1, counted once
    float ax = 0.f, ay = 0.f;
    if (lane < D / 2) {
        float2 hw = __half22float2(g_h16[(size_t)w * (D / 2) + lane]);
        ax = hw.x; ay = hw.y;
    }

    for (int j0 = beg; j0 < end; j0 += 32) {
        int j = j0 + lane;
        int s = 0;
        float e = -INFINITY;
        if (j < end) {
            s = g_esrc[j];
            e = g_as[s] + ad_n;
            e = e > 0.f ? e : SLOPE * e;
        }
        float tm = e;
#pragma unroll
        for (int off = 16; off; off >>= 1) tm = fmaxf(tm, __shfl_xor_sync(0xffffffffu, tm, off));
        float mnew = fmaxf(m, tm);
        float scale = __expf(m - mnew);
        ssum *= scale; ax *= scale; ay *= scale;
        m = mnew;

        float p = (j < end) ? __expf(e - m) : 0.f;
        ssum += p;
        sp_p[wl][lane] = p;
        sp_s[wl][lane] = s;
        __syncwarp();
        int cnt = min(32, end - j0);
        if (lane < D / 2) {
#pragma unroll 8
            for (int k = 0; k < cnt; k++) {
                float pk = sp_p[wl][k];
                int   sk = sp_s[wl][k];
                float2 hv = __half22float2(g_h16[(size_t)sk * (D / 2) + lane]);
                ax += pk * hv.x;
                ay += pk * hv.y;
            }
        }
        __syncwarp();
    }
#pragma unroll
    for (int off = 16; off; off >>= 1) ssum += __shfl_xor_sync(0xffffffffu, ssum, off);
    float inv = 1.f / (ssum + 1e-16f);

    if (!FINAL) {
        float v0 = ax * inv + b[2 * lane];
        float v1 = ay * inv + b[2 * lane + 1];
        float2 o;
        o.x = v0 > 0.f ? v0 : 0.f;
        o.y = v1 > 0.f ? v1 : 0.f;
        ((float2*)g_h1o)[(size_t)w * (D / 2) + lane] = o;
    } else {
        float va = -INFINITY, vb = -INFINITY;
        if (lane < D / 2) {
            va = ax * inv + b[2 * lane];
            vb = ay * inv + b[2 * lane + 1];
        }
        float mx = fmaxf(va, vb);
#pragma unroll
        for (int off = 16; off; off >>= 1) mx = fmaxf(mx, __shfl_xor_sync(0xffffffffu, mx, off));
        float se = (lane < D / 2) ? (__expf(va - mx) + __expf(vb - mx)) : 0.f;
#pragma unroll
        for (int off = 16; off; off >>= 1) se += __shfl_xor_sync(0xffffffffu, se, off);
        float lse = mx + logf(se);
        if (lane < D / 2) {
            float2 o;
            o.x = va - lse;
            o.y = vb - lse;
            ((float2*)out)[(size_t)w * (D / 2) + lane] = o;
        }
    }
}

extern "C" void kernel_launch(void* const* d_in, const int* in_sizes, int n_in,
                              void* d_out, int out_size) {
    const float* x   = (const float*)d_in[0];
    const int*   ei  = (const int*)d_in[1];
    const float* W1  = (const float*)d_in[2];
    const float* as1 = (const float*)d_in[3];
    const float* ad1 = (const float*)d_in[4];
    const float* b1  = (const float*)d_in[5];
    const float* W2  = (const float*)d_in[6];
    const float* as2 = (const float*)d_in[7];
    const float* ad2 = (const float*)d_in[8];
    const float* b2  = (const float*)d_in[9];
    float* out = (float*)d_out;

    static cudaStream_t s2 = nullptr;
    static cudaEvent_t evFork = nullptr, evCSR = nullptr;
    if (!s2) {
        cudaStreamCreateWithFlags(&s2, cudaStreamNonBlocking);
        cudaEventCreateWithFlags(&evFork, cudaEventDisableTiming);
        cudaEventCreateWithFlags(&evCSR, cudaEventDisableTiming);
    }

    const int TB = 256;
    int grid_edges = (NE / 8 + TB - 1) / TB;        // 391
    int grid_warp_nodes = (NN * 32 + TB - 1) / TB;
    int grid_nodes32 = (NN + 31) / 32;

    // fork: CSR build on s2, concurrent with layer-1 GEMM on main.
    // Submission order puts gemm1 4th (ncu profiles the 4th launch).
    cudaEventRecord(evFork, 0);
    cudaStreamWaitEvent(s2, evFork, 0);

    hist_kernel<<<grid_edges, TB, 0, s2>>>(ei);                       // 1
    scan_local_kernel<<<NBLK, SCB, 0, s2>>>();                        // 2
    add_off_kernel<<<NBLK, SCB, 0, s2>>>();                           // 3
    gemm_att_kernel<DI, DH, true><<<grid_nodes32, DH * 4>>>(x, W1, as1, ad1);   // 4 (main)
    scatter_kernel<<<grid_edges, TB, 0, s2>>>(ei);                    // 5
    cudaEventRecord(evCSR, s2);

    cudaStreamWaitEvent(0, evCSR, 0);
    agg_kernel<DH, false><<<grid_warp_nodes, TB>>>(b1, nullptr);      // 6

    gemm_att_kernel<DH, DOUT, false><<<grid_nodes32, DOUT * 4>>>(nullptr, W2, as2, ad2); // 7
    agg_kernel<DOUT, true><<<grid_warp_nodes, TB>>>(b2, out);         // 8
}

// round 13
// speedup vs baseline: 1.8872x; 1.0100x over previous
#include <cuda_runtime.h>
#include <cuda_fp16.h>
#include <math.h>

#define NN 50000
#define NE 800000
#define DI 128
#define DH 64
#define DOUT 40
#define SLOPE 0.2f
#define SCB 1024
#define NBLK 49            // ceil(50000/1024)

// ---------------- scratch ----------------
__device__ __half2 g_h16[NN * (DH / 2)];
__device__ float   g_as[NN];
__device__ float   g_ad[NN];
__device__ float   g_h1o[NN * DH];
__device__ int     g_deg[NN];        // starts zero; re-zeroed by scatter each call
__device__ int     g_rowptr[NN + 1];
__device__ int     g_bsum[NBLK];
__device__ int     g_rank[NE];
__device__ int     g_esrc[NE];

// ---------------- CSR build (real edges only; self loops handled in agg) -----
__global__ void hist_kernel(const int* __restrict__ ei) {
    int t = blockIdx.x * blockDim.x + threadIdx.x;
    if (t >= NE / 8) return;
    int4 a = *(const int4*)&ei[NE + t * 8];
    int4 b = *(const int4*)&ei[NE + t * 8 + 4];
    int r0 = atomicAdd(&g_deg[a.x], 1);
    int r1 = atomicAdd(&g_deg[a.y], 1);
    int r2 = atomicAdd(&g_deg[a.z], 1);
    int r3 = atomicAdd(&g_deg[a.w], 1);
    int r4 = atomicAdd(&g_deg[b.x], 1);
    int r5 = atomicAdd(&g_deg[b.y], 1);
    int r6 = atomicAdd(&g_deg[b.z], 1);
    int r7 = atomicAdd(&g_deg[b.w], 1);
    *(int4*)&g_rank[t * 8]     = make_int4(r0, r1, r2, r3);
    *(int4*)&g_rank[t * 8 + 4] = make_int4(r4, r5, r6, r7);
}

__global__ void scan_local_kernel() {
    __shared__ int wsum[32];
    int t = threadIdx.x, lane = t & 31, wid = t >> 5;
    int i = blockIdx.x * SCB + t;
    int v = (i < NN) ? g_deg[i] : 0;
    int sc = v;
#pragma unroll
    for (int off = 1; off < 32; off <<= 1) {
        int u = __shfl_up_sync(0xffffffffu, sc, off);
        if (lane >= off) sc += u;
    }
    if (lane == 31) wsum[wid] = sc;
    __syncthreads();
    if (wid == 0) {
        int w0 = wsum[lane];
        int s = w0;
#pragma unroll
        for (int off = 1; off < 32; off <<= 1) {
            int u = __shfl_up_sync(0xffffffffu, s, off);
            if (lane >= off) s += u;
        }
        wsum[lane] = s - w0;
    }
    __syncthreads();
    int ex = sc - v + wsum[wid];
    if (i < NN) g_rowptr[i] = ex;
    if (t == SCB - 1) g_bsum[blockIdx.x] = ex + v;
}

__global__ void add_off_kernel() {
    __shared__ int sh[2];
    int t = threadIdx.x, bid = blockIdx.x;
    if (t < 32) {
        int a = (t < NBLK) ? g_bsum[t] : 0;
        int b = (t + 32 < NBLK) ? g_bsum[t + 32] : 0;
        int pa = ((t < bid) ? a : 0) + ((t + 32 < bid) ? b : 0);
        int ta = a + b;
#pragma unroll
        for (int off = 16; off; off >>= 1) {
            pa += __shfl_xor_sync(0xffffffffu, pa, off);
            ta += __shfl_xor_sync(0xffffffffu, ta, off);
        }
        if (t == 0) { sh[0] = pa; sh[1] = ta; }
    }
    __syncthreads();
    int pre = sh[0];
    int i = bid * SCB + t;
    if (i < NN) g_rowptr[i] += pre;
    if (bid == NBLK - 1 && t == 0) g_rowptr[NN] = sh[1];
}

// atomic-free scatter; also re-zeroes g_deg for the next call
__global__ void scatter_kernel(const int* __restrict__ ei) {
    int t = blockIdx.x * blockDim.x + threadIdx.x;
    if (t < NE / 8) {
        int4 s0 = *(const int4*)&ei[t * 8];
        int4 s1 = *(const int4*)&ei[t * 8 + 4];
        int4 d0 = *(const int4*)&ei[NE + t * 8];
        int4 d1 = *(const int4*)&ei[NE + t * 8 + 4];
        int4 r0 = *(const int4*)&g_rank[t * 8];
        int4 r1 = *(const int4*)&g_rank[t * 8 + 4];
        g_esrc[g_rowptr[d0.x] + r0.x] = s0.x;
        g_esrc[g_rowptr[d0.y] + r0.y] = s0.y;
        g_esrc[g_rowptr[d0.z] + r0.z] = s0.z;
        g_esrc[g_rowptr[d0.w] + r0.w] = s0.w;
        g_esrc[g_rowptr[d1.x] + r1.x] = s1.x;
        g_esrc[g_rowptr[d1.y] + r1.y] = s1.y;
        g_esrc[g_rowptr[d1.z] + r1.z] = s1.z;
        g_esrc[g_rowptr[d1.w] + r1.w] = s1.w;
    }
    int stride = gridDim.x * blockDim.x;
    for (int i = t; i < NN; i += stride) g_deg[i] = 0;
}

// ---------------- fused GEMM + att dots + fp16 convert ----------------
// 64-node tile, 256 threads. Warp owns 8 nodes; lane owns column pair (2*lane).
// Per 4-k chunk: 8 LDS.128 (broadcast) + 4 LDG.64 + 64 FFMA -> 84% FFMA slots.
template <int Din, int Dout, bool USE_X>
__global__ __launch_bounds__(256)
void gemm_att_kernel(const float* __restrict__ X, const float* __restrict__ W,
                     const float* __restrict__ asrc, const float* __restrict__ adst) {
    __shared__ float sx[64 * Din];   // x tile, later reused as h tile
    const float* src = USE_X ? X : g_h1o;
    int base = blockIdx.x * 64;
    int tid = threadIdx.x;

    for (int i = tid; i < 64 * (Din / 4); i += 256) {
        int node = base + i / (Din / 4);
        float4 v = (node < NN) ? ((const float4*)src)[(size_t)node * (Din / 4) + (i % (Din / 4))]
                               : make_float4(0.f, 0.f, 0.f, 0.f);
        ((float4*)sx)[i] = v;
    }
    __syncthreads();

    int lane = tid & 31, w = tid >> 5;
    int nb = w * 8;                      // first node of this warp's group
    bool act = lane < Dout / 2;
    const float4* sx4 = (const float4*)sx;
    float accx[8], accy[8];
#pragma unroll
    for (int n = 0; n < 8; n++) { accx[n] = 0.f; accy[n] = 0.f; }

    for (int k = 0; k < Din; k += 4) {
        float2 w0 = make_float2(0.f, 0.f), w1 = w0, w2 = w0, w3 = w0;
        if (act) {
            w0 = *(const float2*)&W[(k + 0) * Dout + 2 * lane];
            w1 = *(const float2*)&W[(k + 1) * Dout + 2 * lane];
            w2 = *(const float2*)&W[(k + 2) * Dout + 2 * lane];
            w3 = *(const float2*)&W[(k + 3) * Dout + 2 * lane];
        }
#pragma unroll
        for (int n = 0; n < 8; n++) {
            float4 xv = sx4[(nb + n) * (Din / 4) + (k >> 2)];
            accx[n] += xv.x * w0.x + xv.y * w1.x + xv.z * w2.x + xv.w * w3.x;
            accy[n] += xv.x * w0.y + xv.y * w1.y + xv.z * w2.y + xv.w * w3.y;
        }
    }
    __syncthreads();                 // done reading sx

    float* hacc = sx;                // reuse as h tile [64][Dout]
    if (act) {
#pragma unroll
        for (int n = 0; n < 8; n++) {
            hacc[(nb + n) * Dout + 2 * lane]     = accx[n];
            hacc[(nb + n) * Dout + 2 * lane + 1] = accy[n];
        }
    }
    __syncthreads();

    // fp16 conversion (coalesced half2 stores)
    for (int idx = tid; idx < 64 * (Dout / 2); idx += 256) {
        int node = idx / (Dout / 2), c = idx % (Dout / 2);
        if (base + node < NN) {
            float2 v = make_float2(hacc[node * Dout + 2 * c], hacc[node * Dout + 2 * c + 1]);
            g_h16[(size_t)(base + node) * (Dout / 2) + c] = __float22half2_rn(v);
        }
    }

    // att dots: warp per node
    for (int node = w; node < 64; node += 8) {
        float sa = 0.f, sd = 0.f;
        for (int c = lane; c < Dout; c += 32) {
            float h = hacc[node * Dout + c];
            sa += h * asrc[c];
            sd += h * adst[c];
        }
#pragma unroll
        for (int off = 16; off; off >>= 1) {
            sa += __shfl_down_sync(0xffffffffu, sa, off);
            sd += __shfl_down_sync(0xffffffffu, sd, off);
        }
        if (lane == 0 && base + node < NN) {
            g_as[base + node] = sa;
            g_ad[base + node] = sd;
        }
    }
}

// ---------------- fused online-softmax aggregation (+epilogue) ----------------
// self loop folded into init: m=e_self; ssum=1 contributed by lane 0 ONLY.
template <int D, bool FINAL>
__global__ void agg_kernel(const float* __restrict__ b, float* __restrict__ out) {
    __shared__ float sp_p[8][32];
    __shared__ int   sp_s[8][32];
    int wl = threadIdx.x >> 5;
    int w = (blockIdx.x * blockDim.x + threadIdx.x) >> 5;
    int lane = threadIdx.x & 31;
    if (w >= NN) return;
    int beg = g_rowptr[w];
    int end = g_rowptr[w + 1];
    float ad_n = g_ad[w];

    float es = g_as[w] + ad_n;
    es = es > 0.f ? es : SLOPE * es;
    float m = es;
    float ssum = (lane == 0) ? 1.f : 0.f;
    float ax = 0.f, ay = 0.f;
    if (lane < D / 2) {
        float2 hw = __half22float2(g_h16[(size_t)w * (D / 2) + lane]);
        ax = hw.x; ay = hw.y;
    }

    for (int j0 = beg; j0 < end; j0 += 32) {
        int j = j0 + lane;
        int s = 0;
        float e = -INFINITY;
        if (j < end) {
            s = g_esrc[j];
            e = g_as[s] + ad_n;
            e = e > 0.f ? e : SLOPE * e;
        }
        float tm = e;
#pragma unroll
        for (int off = 16; off; off >>= 1) tm = fmaxf(tm, __shfl_xor_sync(0xffffffffu, tm, off));
        float mnew = fmaxf(m, tm);
        float scale = __expf(m - mnew);
        ssum *= scale; ax *= scale; ay *= scale;
        m = mnew;

        float p = (j < end) ? __expf(e - m) : 0.f;
        ssum += p;
        sp_p[wl][lane] = p;
        sp_s[wl][lane] = s;
        __syncwarp();
        int cnt = min(32, end - j0);
        if (lane < D / 2) {
#pragma unroll 8
            for (int k = 0; k < cnt; k++) {
                float pk = sp_p[wl][k];
                int   sk = sp_s[wl][k];
                float2 hv = __half22float2(g_h16[(size_t)sk * (D / 2) + lane]);
                ax += pk * hv.x;
                ay += pk * hv.y;
            }
        }
        __syncwarp();
    }
#pragma unroll
    for (int off = 16; off; off >>= 1) ssum += __shfl_xor_sync(0xffffffffu, ssum, off);
    float inv = 1.f / (ssum + 1e-16f);

    if (!FINAL) {
        float v0 = ax * inv + b[2 * lane];
        float v1 = ay * inv + b[2 * lane + 1];
        float2 o;
        o.x = v0 > 0.f ? v0 : 0.f;
        o.y = v1 > 0.f ? v1 : 0.f;
        ((float2*)g_h1o)[(size_t)w * (D / 2) + lane] = o;
    } else {
        float va = -INFINITY, vb = -INFINITY;
        if (lane < D / 2) {
            va = ax * inv + b[2 * lane];
            vb = ay * inv + b[2 * lane + 1];
        }
        float mx = fmaxf(va, vb);
#pragma unroll
        for (int off = 16; off; off >>= 1) mx = fmaxf(mx, __shfl_xor_sync(0xffffffffu, mx, off));
        float se = (lane < D / 2) ? (__expf(va - mx) + __expf(vb - mx)) : 0.f;
#pragma unroll
        for (int off = 16; off; off >>= 1) se += __shfl_xor_sync(0xffffffffu, se, off);
        float lse = mx + logf(se);
        if (lane < D / 2) {
            float2 o;
            o.x = va - lse;
            o.y = vb - lse;
            ((float2*)out)[(size_t)w * (D / 2) + lane] = o;
        }
    }
}

extern "C" void kernel_launch(void* const* d_in, const int* in_sizes, int n_in,
                              void* d_out, int out_size) {
    const float* x   = (const float*)d_in[0];
    const int*   ei  = (const int*)d_in[1];
    const float* W1  = (const float*)d_in[2];
    const float* as1 = (const float*)d_in[3];
    const float* ad1 = (const float*)d_in[4];
    const float* b1  = (const float*)d_in[5];
    const float* W2  = (const float*)d_in[6];
    const float* as2 = (const float*)d_in[7];
    const float* ad2 = (const float*)d_in[8];
    const float* b2  = (const float*)d_in[9];
    float* out = (float*)d_out;

    static cudaStream_t s2 = nullptr;
    static cudaEvent_t evFork = nullptr, evCSR = nullptr;
    if (!s2) {
        cudaStreamCreateWithFlags(&s2, cudaStreamNonBlocking);
        cudaEventCreateWithFlags(&evFork, cudaEventDisableTiming);
        cudaEventCreateWithFlags(&evCSR, cudaEventDisableTiming);
    }

    const int TB = 256;
    int grid_edges = (NE / 8 + TB - 1) / TB;        // 391
    int grid_warp_nodes = (NN * 32 + TB - 1) / TB;
    int grid_nodes64 = (NN + 63) / 64;

    // fork: CSR build on s2, concurrent with layer-1 GEMM on main.
    // Submission order keeps gemm1 4th (profiled launch).
    cudaEventRecord(evFork, 0);
    cudaStreamWaitEvent(s2, evFork, 0);

    hist_kernel<<<grid_edges, TB, 0, s2>>>(ei);                       // 1
    scan_local_kernel<<<NBLK, SCB, 0, s2>>>();                        // 2
    add_off_kernel<<<NBLK, SCB, 0, s2>>>();                           // 3
    gemm_att_kernel<DI, DH, true><<<grid_nodes64, 256>>>(x, W1, as1, ad1);   // 4 (main)
    scatter_kernel<<<grid_edges, TB, 0, s2>>>(ei);                    // 5
    cudaEventRecord(evCSR, s2);

    cudaStreamWaitEvent(0, evCSR, 0);
    agg_kernel<DH, false><<<grid_warp_nodes, TB>>>(b1, nullptr);      // 6

    gemm_att_kernel<DH, DOUT, false><<<grid_nodes64, 256>>>(nullptr, W2, as2, ad2); // 7
    agg_kernel<DOUT, true><<<grid_warp_nodes, TB>>>(b2, out);         // 8
}